// round 10
// baseline (speedup 1.0000x reference)
#include <cuda_runtime.h>
#include <cuda_fp16.h>

#define N_NODES 100000
#define N_EDGES_MAX 1600000
#define IN_DIM  64
#define HID     32

// Scratch: __device__ globals (no allocation allowed in kernel_launch)
__device__ __align__(128) __half g_h[N_NODES * HID];  // (XW)*norm_src, fp16
__device__ float g_degout[N_NODES];
__device__ float g_degin[N_NODES];
__device__ int   g_off[N_NODES];
__device__ int   g_cursor[N_NODES];
__device__ int   g_total;
__device__ int   g_csr[N_EDGES_MAX];   // src ids bucketed by dst (buckets contiguous, order arbitrary)

// ---------------------------------------------------------------------------
// 1) FUSED: even blocks gemm_raw (FMA-bound), odd blocks degree atomics
//    (LTS-bound) -> concurrent pipe usage.
// ---------------------------------------------------------------------------
#define GEMM_ROWS 64
__global__ void __launch_bounds__(256, 2)
fused_gemm_deg_kernel(const float4* __restrict__ X4,
                      const float* __restrict__ W,
                      const int4* __restrict__ src4,
                      const int4* __restrict__ dst4, int n, int e) {
    __shared__ float4 xs4[GEMM_ROWS * (IN_DIM / 4)];   // 16KB (gemm role only)

    int t = threadIdx.x;

    if (blockIdx.x & 1) {
        // ---- degree role ----
        int bid = blockIdx.x >> 1;
        int e4 = e >> 2;
        int i = bid * 256 + t;
        if (i < e4) {
            int4 s = src4[i];
            int4 d = dst4[i];
            atomicAdd(&g_degout[s.x], 1.f); atomicAdd(&g_degout[s.y], 1.f);
            atomicAdd(&g_degout[s.z], 1.f); atomicAdd(&g_degout[s.w], 1.f);
            atomicAdd(&g_degin[d.x], 1.f);  atomicAdd(&g_degin[d.y], 1.f);
            atomicAdd(&g_degin[d.z], 1.f);  atomicAdd(&g_degin[d.w], 1.f);
        }
        if (i == 0) {   // tail (e % 4)
            const int* src = (const int*)src4;
            const int* dst = (const int*)dst4;
            for (int k = e4 * 4; k < e; k++) {
                atomicAdd(&g_degout[src[k]], 1.f);
                atomicAdd(&g_degin [dst[k]], 1.f);
            }
        }
        return;
    }

    // ---- gemm role: h_raw = X @ W -> fp16 (norm applied later) ----
    int bid  = blockIdx.x >> 1;
    int lane = t & 31;
    int warp = t >> 5;
    int row0 = bid * GEMM_ROWS;

    float w[IN_DIM];
#pragma unroll
    for (int k = 0; k < IN_DIM; k++)
        w[k] = __ldg(W + k * HID + lane);

#pragma unroll
    for (int i = t; i < GEMM_ROWS * (IN_DIM / 4); i += 256) {
        int r = i >> 4;
        if (row0 + r < n) xs4[i] = X4[row0 * (IN_DIM / 4) + i];
    }
    __syncthreads();

#pragma unroll
    for (int rr = 0; rr < 8; rr++) {
        int rl  = warp * 8 + rr;
        int row = row0 + rl;
        if (row >= n) break;

        const float4* xr = xs4 + rl * (IN_DIM / 4);
        float acc = 0.f;
#pragma unroll
        for (int k4 = 0; k4 < IN_DIM / 4; k4++) {
            float4 x = xr[k4];          // broadcast LDS.128
            acc += x.x * w[k4 * 4 + 0];
            acc += x.y * w[k4 * 4 + 1];
            acc += x.z * w[k4 * 4 + 2];
            acc += x.w * w[k4 * 4 + 3];
        }
        g_h[row * HID + lane] = __float2half(acc);
    }
}

// ---------------------------------------------------------------------------
// 2) FUSED alloc + norm_h:
//    a) bucket allocation: warp-scan of 32 degrees + one atomicAdd on g_total
//       (offsets contiguous per dst node; global order irrelevant for agg)
//    b) h[row,:] *= rsqrt(max(degout[row],1))  (uint4 = 8 halfs/thread)
// ---------------------------------------------------------------------------
__global__ void alloc_norm_kernel(int n) {
    int gtid = blockIdx.x * blockDim.x + threadIdx.x;
    int lane = threadIdx.x & 31;

    // ---- a) allocation: first ceil(n/32) warps, one node per lane ----
    int wid = gtid >> 5;
    int node = wid * 32 + lane;
    if (wid * 32 < n) {
        int deg = (node < n) ? (int)g_degin[node] : 0;
        int incl = deg;
#pragma unroll
        for (int o = 1; o < 32; o <<= 1) {
            int y = __shfl_up_sync(~0u, incl, o);
            if (lane >= o) incl += y;
        }
        int wsum = __shfl_sync(~0u, incl, 31);
        int base = 0;
        if (lane == 31) base = atomicAdd(&g_total, wsum);
        base = __shfl_sync(~0u, base, 31);
        if (node < n) {
            int off = base + incl - deg;
            g_off[node]    = off;
            g_cursor[node] = off;
        }
    }

    // ---- b) norm_h ----
    if (gtid < n * (HID / 8)) {
        int row = gtid >> 2;
        float nrm = rsqrtf(fmaxf(g_degout[row], 1.f));
        __half2 nh = __float2half2_rn(nrm);
        uint4 raw = reinterpret_cast<uint4*>(g_h)[gtid];
        __half2* h = reinterpret_cast<__half2*>(&raw);
        h[0] = __hmul2(h[0], nh);
        h[1] = __hmul2(h[1], nh);
        h[2] = __hmul2(h[2], nh);
        h[3] = __hmul2(h[3], nh);
        reinterpret_cast<uint4*>(g_h)[gtid] = raw;
    }
}

// ---------------------------------------------------------------------------
// 3) fill CSR buckets: csr[cursor[dst]++] = src   (4 edges/thread, int4)
// ---------------------------------------------------------------------------
__global__ void fill_kernel(const int4* __restrict__ src4,
                            const int4* __restrict__ dst4, int e) {
    int e4 = e >> 2;
    int i = blockIdx.x * blockDim.x + threadIdx.x;
    if (i < e4) {
        int4 s = src4[i];
        int4 d = dst4[i];
        g_csr[atomicAdd(&g_cursor[d.x], 1)] = s.x;
        g_csr[atomicAdd(&g_cursor[d.y], 1)] = s.y;
        g_csr[atomicAdd(&g_cursor[d.z], 1)] = s.z;
        g_csr[atomicAdd(&g_cursor[d.w], 1)] = s.w;
    }
    if (i == 0) {   // tail (e % 4)
        const int* src = (const int*)src4;
        const int* dst = (const int*)dst4;
        for (int k = e4 * 4; k < e; k++)
            g_csr[atomicAdd(&g_cursor[dst[k]], 1)] = src[k];
    }
}

// ---------------------------------------------------------------------------
// 4) aggregate + finalize: warp per dst node, lane = column.
//    out[d] = relu( (sum_{s in bucket(d)} h[s]) * norm_dst + b )
//    Pure gather: 2 sectors/edge (fp16), zero atomics, fin fused.
// ---------------------------------------------------------------------------
__global__ void agg_kernel(float* __restrict__ out,
                           const float* __restrict__ b, int n) {
    int node = (blockIdx.x * blockDim.x + threadIdx.x) >> 5;
    int lane = threadIdx.x & 31;
    if (node >= n) return;

    int start = g_off[node];
    int deg   = (int)g_degin[node];

    float acc = 0.f;
    for (int kb = 0; kb < deg; kb += 32) {
        int rem = deg - kb;
        int cnt = rem < 32 ? rem : 32;
        int myidx = (lane < cnt) ? g_csr[start + kb + lane] : 0;
        int j = 0;
#pragma unroll 4
        for (; j + 4 <= cnt; j += 4) {
            int s0 = __shfl_sync(~0u, myidx, j + 0);
            int s1 = __shfl_sync(~0u, myidx, j + 1);
            int s2 = __shfl_sync(~0u, myidx, j + 2);
            int s3 = __shfl_sync(~0u, myidx, j + 3);
            float v0 = __half2float(g_h[s0 * HID + lane]);
            float v1 = __half2float(g_h[s1 * HID + lane]);
            float v2 = __half2float(g_h[s2 * HID + lane]);
            float v3 = __half2float(g_h[s3 * HID + lane]);
            acc += v0 + v1 + v2 + v3;
        }
        for (; j < cnt; j++) {
            int s = __shfl_sync(~0u, myidx, j);
            acc += __half2float(g_h[s * HID + lane]);
        }
    }

    float nrm = rsqrtf(fmaxf((float)deg, 1.f));
    out[node * HID + lane] = fmaxf(acc * nrm + __ldg(b + lane), 0.f);
}

// ---------------------------------------------------------------------------
extern "C" void kernel_launch(void* const* d_in, const int* in_sizes, int n_in,
                              void* d_out, int out_size) {
    const float* features = (const float*)d_in[0];   // [N, 64]
    const int*   src      = (const int*)  d_in[1];   // [E]
    const int*   dst      = (const int*)  d_in[2];   // [E]
    const float* W        = (const float*)d_in[3];   // [64, 32]
    const float* b        = (const float*)d_in[4];   // [32]
    float*       out      = (float*)d_out;           // [N, 32]

    int n = in_sizes[0] / IN_DIM;                    // 100000
    int e = in_sizes[1];                             // 1600000

    // 0) reset counters via memset nodes (out NOT zeroed: agg overwrites all)
    void* p_degout = nullptr; void* p_degin = nullptr; void* p_total = nullptr;
    cudaGetSymbolAddress(&p_degout, g_degout);
    cudaGetSymbolAddress(&p_degin,  g_degin);
    cudaGetSymbolAddress(&p_total,  g_total);
    cudaMemsetAsync(p_degout, 0, (size_t)n * sizeof(float), 0);
    cudaMemsetAsync(p_degin,  0, (size_t)n * sizeof(float), 0);
    cudaMemsetAsync(p_total,  0, sizeof(int), 0);

    // 1) fused gemm_raw + degrees (parity-interleaved block roles)
    int gemm_blocks = (n + GEMM_ROWS - 1) / GEMM_ROWS;
    int deg_blocks  = ((e >> 2) + 255) / 256;
    int total_blocks = 2 * (gemm_blocks > deg_blocks ? gemm_blocks : deg_blocks);
    fused_gemm_deg_kernel<<<total_blocks, 256>>>(
        (const float4*)features, W, (const int4*)src, (const int4*)dst, n, e);

    // 2) bucket allocation + norm_src applied to h
    int an_threads = n * (HID / 8);                  // 400K, covers alloc warps too
    alloc_norm_kernel<<<(an_threads + 255) / 256, 256>>>(n);

    // 3) fill CSR buckets
    fill_kernel<<<((e >> 2) + 255) / 256, 256>>>((const int4*)src,
                                                 (const int4*)dst, e);

    // 4) aggregate + normalize + bias + relu (warp per node)
    agg_kernel<<<(n * 32 + 255) / 256, 256>>>(out, b, n);
}

// round 13
// speedup vs baseline: 1.0326x; 1.0326x over previous
#include <cuda_runtime.h>
#include <cuda_fp16.h>

#define N_NODES 100000
#define N_EDGES_MAX 1600000
#define IN_DIM  64
#define HID     32

// Scratch: __device__ globals (no allocation allowed in kernel_launch)
__device__ __align__(128) __half g_h[N_NODES * HID];  // (XW)*norm_src, fp16
__device__ float g_degout[N_NODES];
__device__ float g_degin[N_NODES];
__device__ int   g_off[N_NODES];
__device__ int   g_cursor[N_NODES];
__device__ int   g_total;
__device__ int   g_csr[N_EDGES_MAX];   // src ids bucketed by dst

// ---------------------------------------------------------------------------
// 1) FUSED: even blocks gemm_raw (FMA-bound), odd blocks degree atomics
//    (LTS-bound) -> concurrent pipe usage.
// ---------------------------------------------------------------------------
#define GEMM_ROWS 64
__global__ void __launch_bounds__(256, 2)
fused_gemm_deg_kernel(const float4* __restrict__ X4,
                      const float* __restrict__ W,
                      const int4* __restrict__ src4,
                      const int4* __restrict__ dst4, int n, int e) {
    __shared__ float4 xs4[GEMM_ROWS * (IN_DIM / 4)];

    int t = threadIdx.x;

    if (blockIdx.x & 1) {
        // ---- degree role ----
        int bid = blockIdx.x >> 1;
        int e4 = e >> 2;
        int i = bid * 256 + t;
        if (i < e4) {
            int4 s = src4[i];
            int4 d = dst4[i];
            atomicAdd(&g_degout[s.x], 1.f); atomicAdd(&g_degout[s.y], 1.f);
            atomicAdd(&g_degout[s.z], 1.f); atomicAdd(&g_degout[s.w], 1.f);
            atomicAdd(&g_degin[d.x], 1.f);  atomicAdd(&g_degin[d.y], 1.f);
            atomicAdd(&g_degin[d.z], 1.f);  atomicAdd(&g_degin[d.w], 1.f);
        }
        if (i == 0) {
            const int* src = (const int*)src4;
            const int* dst = (const int*)dst4;
            for (int k = e4 * 4; k < e; k++) {
                atomicAdd(&g_degout[src[k]], 1.f);
                atomicAdd(&g_degin [dst[k]], 1.f);
            }
        }
        return;
    }

    // ---- gemm role: h_raw = X @ W -> fp16 ----
    int bid  = blockIdx.x >> 1;
    int lane = t & 31;
    int warp = t >> 5;
    int row0 = bid * GEMM_ROWS;

    float w[IN_DIM];
#pragma unroll
    for (int k = 0; k < IN_DIM; k++)
        w[k] = __ldg(W + k * HID + lane);

#pragma unroll
    for (int i = t; i < GEMM_ROWS * (IN_DIM / 4); i += 256) {
        int r = i >> 4;
        if (row0 + r < n) xs4[i] = X4[row0 * (IN_DIM / 4) + i];
    }
    __syncthreads();

#pragma unroll
    for (int rr = 0; rr < 8; rr++) {
        int rl  = warp * 8 + rr;
        int row = row0 + rl;
        if (row >= n) break;

        const float4* xr = xs4 + rl * (IN_DIM / 4);
        float acc = 0.f;
#pragma unroll
        for (int k4 = 0; k4 < IN_DIM / 4; k4++) {
            float4 x = xr[k4];
            acc += x.x * w[k4 * 4 + 0];
            acc += x.y * w[k4 * 4 + 1];
            acc += x.z * w[k4 * 4 + 2];
            acc += x.w * w[k4 * 4 + 3];
        }
        g_h[row * HID + lane] = __float2half(acc);
    }
}

// ---------------------------------------------------------------------------
// 2) FUSED alloc + norm_h (warp-scan bucket allocation, no prefix-scan kernel)
// ---------------------------------------------------------------------------
__global__ void alloc_norm_kernel(int n) {
    int gtid = blockIdx.x * blockDim.x + threadIdx.x;
    int lane = threadIdx.x & 31;

    int wid = gtid >> 5;
    int node = wid * 32 + lane;
    if (wid * 32 < n) {
        int deg = (node < n) ? (int)g_degin[node] : 0;
        int incl = deg;
#pragma unroll
        for (int o = 1; o < 32; o <<= 1) {
            int y = __shfl_up_sync(~0u, incl, o);
            if (lane >= o) incl += y;
        }
        int wsum = __shfl_sync(~0u, incl, 31);
        int base = 0;
        if (lane == 31) base = atomicAdd(&g_total, wsum);
        base = __shfl_sync(~0u, base, 31);
        if (node < n) {
            int off = base + incl - deg;
            g_off[node]    = off;
            g_cursor[node] = off;
        }
    }

    if (gtid < n * (HID / 8)) {
        int row = gtid >> 2;
        float nrm = rsqrtf(fmaxf(g_degout[row], 1.f));
        __half2 nh = __float2half2_rn(nrm);
        uint4 raw = reinterpret_cast<uint4*>(g_h)[gtid];
        __half2* h = reinterpret_cast<__half2*>(&raw);
        h[0] = __hmul2(h[0], nh);
        h[1] = __hmul2(h[1], nh);
        h[2] = __hmul2(h[2], nh);
        h[3] = __hmul2(h[3], nh);
        reinterpret_cast<uint4*>(g_h)[gtid] = raw;
    }
}

// ---------------------------------------------------------------------------
// 3) fill CSR buckets: csr[cursor[dst]++] = src   (4 edges/thread, int4)
// ---------------------------------------------------------------------------
__global__ void fill_kernel(const int4* __restrict__ src4,
                            const int4* __restrict__ dst4, int e) {
    int e4 = e >> 2;
    int i = blockIdx.x * blockDim.x + threadIdx.x;
    if (i < e4) {
        int4 s = src4[i];
        int4 d = dst4[i];
        g_csr[atomicAdd(&g_cursor[d.x], 1)] = s.x;
        g_csr[atomicAdd(&g_cursor[d.y], 1)] = s.y;
        g_csr[atomicAdd(&g_cursor[d.z], 1)] = s.z;
        g_csr[atomicAdd(&g_cursor[d.w], 1)] = s.w;
    }
    if (i == 0) {
        const int* src = (const int*)src4;
        const int* dst = (const int*)dst4;
        for (int k = e4 * 4; k < e; k++)
            g_csr[atomicAdd(&g_cursor[dst[k]], 1)] = src[k];
    }
}

// ---------------------------------------------------------------------------
// 4) aggregate + finalize: warp per dst node, VECTORIZED:
//    lane = (sub=lane>>3 edge-in-group, c=(lane&7)*4 col-group).
//    Per 4-edge group each lane does ONE uint2 (4-half) gather; no shfl in
//    the inner loop. Cross-sub reduction (8 shfl_xor) once per node.
// ---------------------------------------------------------------------------
__global__ void agg_kernel(float* __restrict__ out,
                           const float* __restrict__ b, int n) {
    int node = (blockIdx.x * blockDim.x + threadIdx.x) >> 5;
    int lane = threadIdx.x & 31;
    if (node >= n) return;

    int start = g_off[node];
    int deg   = (int)g_degin[node];

    int sub = lane >> 3;            // 0..3: which edge of the group
    int c   = (lane & 7) << 2;      // half-column offset 0,4,...,28

    float ax = 0.f, ay = 0.f, az = 0.f, aw = 0.f;

#pragma unroll 2
    for (int kb = 0; kb < deg; kb += 4) {
        int el = kb + sub;
        if (el < deg) {
            int idx = g_csr[start + el];
            uint2 raw = *reinterpret_cast<const uint2*>(g_h + idx * HID + c);
            float2 f01 = __half22float2(*reinterpret_cast<__half2*>(&raw.x));
            float2 f23 = __half22float2(*reinterpret_cast<__half2*>(&raw.y));
            ax += f01.x; ay += f01.y; az += f23.x; aw += f23.y;
        }
    }

    // reduce across the 4 sub-groups (lanes differing in bits 3,4)
#pragma unroll
    for (int o = 8; o <= 16; o <<= 1) {
        ax += __shfl_xor_sync(~0u, ax, o);
        ay += __shfl_xor_sync(~0u, ay, o);
        az += __shfl_xor_sync(~0u, az, o);
        aw += __shfl_xor_sync(~0u, aw, o);
    }

    // lanes 0..7 hold the full sums for col groups 0..7
    if (lane < 8) {
        float nrm = rsqrtf(fmaxf((float)deg, 1.f));
        float4 bb = *reinterpret_cast<const float4*>(b + c);
        float4 v;
        v.x = fmaxf(ax * nrm + bb.x, 0.f);
        v.y = fmaxf(ay * nrm + bb.y, 0.f);
        v.z = fmaxf(az * nrm + bb.z, 0.f);
        v.w = fmaxf(aw * nrm + bb.w, 0.f);
        *reinterpret_cast<float4*>(out + node * HID + c) = v;
    }
}

// ---------------------------------------------------------------------------
extern "C" void kernel_launch(void* const* d_in, const int* in_sizes, int n_in,
                              void* d_out, int out_size) {
    const float* features = (const float*)d_in[0];   // [N, 64]
    const int*   src      = (const int*)  d_in[1];   // [E]
    const int*   dst      = (const int*)  d_in[2];   // [E]
    const float* W        = (const float*)d_in[3];   // [64, 32]
    const float* b        = (const float*)d_in[4];   // [32]
    float*       out      = (float*)d_out;           // [N, 32]

    int n = in_sizes[0] / IN_DIM;                    // 100000
    int e = in_sizes[1];                             // 1600000

    // 0) reset counters via memset nodes
    void* p_degout = nullptr; void* p_degin = nullptr; void* p_total = nullptr;
    cudaGetSymbolAddress(&p_degout, g_degout);
    cudaGetSymbolAddress(&p_degin,  g_degin);
    cudaGetSymbolAddress(&p_total,  g_total);
    cudaMemsetAsync(p_degout, 0, (size_t)n * sizeof(float), 0);
    cudaMemsetAsync(p_degin,  0, (size_t)n * sizeof(float), 0);
    cudaMemsetAsync(p_total,  0, sizeof(int), 0);

    // 1) fused gemm_raw + degrees
    int gemm_blocks = (n + GEMM_ROWS - 1) / GEMM_ROWS;
    int deg_blocks  = ((e >> 2) + 255) / 256;
    int total_blocks = 2 * (gemm_blocks > deg_blocks ? gemm_blocks : deg_blocks);
    fused_gemm_deg_kernel<<<total_blocks, 256>>>(
        (const float4*)features, W, (const int4*)src, (const int4*)dst, n, e);

    // 2) bucket allocation + norm_src applied to h
    int an_threads = n * (HID / 8);
    alloc_norm_kernel<<<(an_threads + 255) / 256, 256>>>(n);

    // 3) fill CSR buckets
    fill_kernel<<<((e >> 2) + 255) / 256, 256>>>((const int4*)src,
                                                 (const int4*)dst, e);

    // 4) aggregate + normalize + bias + relu (warp per node, vectorized)
    agg_kernel<<<(n * 32 + 255) / 256, 256>>>(out, b, n);
}

// round 16
// speedup vs baseline: 1.1493x; 1.1131x over previous
#include <cuda_runtime.h>
#include <cuda_fp16.h>

#define N_NODES 100000
#define N_EDGES_MAX 1600000
#define IN_DIM  64
#define HID     32

// Scratch: __device__ globals (no allocation allowed in kernel_launch)
__device__ __align__(128) __half g_h[N_NODES * HID];  // (XW)*norm_src, fp16
__device__ float g_degout[N_NODES];
__device__ float g_degin[N_NODES];
__device__ int   g_off[N_NODES];
__device__ int   g_cursor[N_NODES];
__device__ int   g_total;
__device__ int   g_csr[N_EDGES_MAX];   // src ids bucketed by dst

// ---------------------------------------------------------------------------
// 1) FUSED: even blocks gemm_raw (FMA-bound), odd blocks degree atomics
//    (LTS-bound) -> concurrent pipe usage.
// ---------------------------------------------------------------------------
#define GEMM_ROWS 64
__global__ void __launch_bounds__(256, 2)
fused_gemm_deg_kernel(const float4* __restrict__ X4,
                      const float* __restrict__ W,
                      const int4* __restrict__ src4,
                      const int4* __restrict__ dst4, int n, int e) {
    __shared__ float4 xs4[GEMM_ROWS * (IN_DIM / 4)];

    int t = threadIdx.x;

    if (blockIdx.x & 1) {
        // ---- degree role ----
        int bid = blockIdx.x >> 1;
        int e4 = e >> 2;
        int i = bid * 256 + t;
        if (i < e4) {
            int4 s = src4[i];
            int4 d = dst4[i];
            atomicAdd(&g_degout[s.x], 1.f); atomicAdd(&g_degout[s.y], 1.f);
            atomicAdd(&g_degout[s.z], 1.f); atomicAdd(&g_degout[s.w], 1.f);
            atomicAdd(&g_degin[d.x], 1.f);  atomicAdd(&g_degin[d.y], 1.f);
            atomicAdd(&g_degin[d.z], 1.f);  atomicAdd(&g_degin[d.w], 1.f);
        }
        if (i == 0) {
            const int* src = (const int*)src4;
            const int* dst = (const int*)dst4;
            for (int k = e4 * 4; k < e; k++) {
                atomicAdd(&g_degout[src[k]], 1.f);
                atomicAdd(&g_degin [dst[k]], 1.f);
            }
        }
        return;
    }

    // ---- gemm role: h_raw = X @ W -> fp16 ----
    int bid  = blockIdx.x >> 1;
    int lane = t & 31;
    int warp = t >> 5;
    int row0 = bid * GEMM_ROWS;

    float w[IN_DIM];
#pragma unroll
    for (int k = 0; k < IN_DIM; k++)
        w[k] = __ldg(W + k * HID + lane);

#pragma unroll
    for (int i = t; i < GEMM_ROWS * (IN_DIM / 4); i += 256) {
        int r = i >> 4;
        if (row0 + r < n) xs4[i] = X4[row0 * (IN_DIM / 4) + i];
    }
    __syncthreads();

#pragma unroll
    for (int rr = 0; rr < 8; rr++) {
        int rl  = warp * 8 + rr;
        int row = row0 + rl;
        if (row >= n) break;

        const float4* xr = xs4 + rl * (IN_DIM / 4);
        float acc = 0.f;
#pragma unroll
        for (int k4 = 0; k4 < IN_DIM / 4; k4++) {
            float4 x = xr[k4];
            acc += x.x * w[k4 * 4 + 0];
            acc += x.y * w[k4 * 4 + 1];
            acc += x.z * w[k4 * 4 + 2];
            acc += x.w * w[k4 * 4 + 3];
        }
        g_h[row * HID + lane] = __float2half(acc);
    }
}

// ---------------------------------------------------------------------------
// 2) FUSED alloc + norm_h (warp-scan bucket allocation, no prefix-scan kernel)
// ---------------------------------------------------------------------------
__global__ void alloc_norm_kernel(int n) {
    int gtid = blockIdx.x * blockDim.x + threadIdx.x;
    int lane = threadIdx.x & 31;

    int wid = gtid >> 5;
    int node = wid * 32 + lane;
    if (wid * 32 < n) {
        int deg = (node < n) ? (int)g_degin[node] : 0;
        int incl = deg;
#pragma unroll
        for (int o = 1; o < 32; o <<= 1) {
            int y = __shfl_up_sync(~0u, incl, o);
            if (lane >= o) incl += y;
        }
        int wsum = __shfl_sync(~0u, incl, 31);
        int base = 0;
        if (lane == 31) base = atomicAdd(&g_total, wsum);
        base = __shfl_sync(~0u, base, 31);
        if (node < n) {
            int off = base + incl - deg;
            g_off[node]    = off;
            g_cursor[node] = off;
        }
    }

    if (gtid < n * (HID / 8)) {
        int row = gtid >> 2;
        float nrm = rsqrtf(fmaxf(g_degout[row], 1.f));
        __half2 nh = __float2half2_rn(nrm);
        uint4 raw = reinterpret_cast<uint4*>(g_h)[gtid];
        __half2* h = reinterpret_cast<__half2*>(&raw);
        h[0] = __hmul2(h[0], nh);
        h[1] = __hmul2(h[1], nh);
        h[2] = __hmul2(h[2], nh);
        h[3] = __hmul2(h[3], nh);
        reinterpret_cast<uint4*>(g_h)[gtid] = raw;
    }
}

// ---------------------------------------------------------------------------
// 3) fill CSR buckets: csr[cursor[dst]++] = src   (4 edges/thread, int4)
// ---------------------------------------------------------------------------
__global__ void fill_kernel(const int4* __restrict__ src4,
                            const int4* __restrict__ dst4, int e) {
    int e4 = e >> 2;
    int i = blockIdx.x * blockDim.x + threadIdx.x;
    if (i < e4) {
        int4 s = src4[i];
        int4 d = dst4[i];
        g_csr[atomicAdd(&g_cursor[d.x], 1)] = s.x;
        g_csr[atomicAdd(&g_cursor[d.y], 1)] = s.y;
        g_csr[atomicAdd(&g_cursor[d.z], 1)] = s.z;
        g_csr[atomicAdd(&g_cursor[d.w], 1)] = s.w;
    }
    if (i == 0) {
        const int* src = (const int*)src4;
        const int* dst = (const int*)dst4;
        for (int k = e4 * 4; k < e; k++)
            g_csr[atomicAdd(&g_cursor[dst[k]], 1)] = src[k];
    }
}

// ---------------------------------------------------------------------------
// 4) aggregate + finalize: 8 THREADS PER NODE, thread owns col-group
//    c=(tid&7)*4. Serial walk over the node's bucket: per edge 1 broadcast
//    idx LDG + 1 uint2 gather + adds. NO shuffles, NO reduction epilogue.
//    Warp covers 4 consecutive nodes -> coalesced float4 stores.
// ---------------------------------------------------------------------------
__global__ void agg_kernel(float* __restrict__ out,
                           const float* __restrict__ b, int n) {
    int gid  = blockIdx.x * blockDim.x + threadIdx.x;
    int node = gid >> 3;
    int c    = (gid & 7) << 2;        // half-col offset 0,4,...,28
    if (node >= n) return;

    int start = g_off[node];
    int deg   = (int)g_degin[node];
    const int* __restrict__ bucket = g_csr + start;

    float ax = 0.f, ay = 0.f, az = 0.f, aw = 0.f;

    int j = 0;
    // unrolled by 2: two independent idx+gather chains in flight
    for (; j + 2 <= deg; j += 2) {
        int i0 = __ldg(bucket + j);
        int i1 = __ldg(bucket + j + 1);
        uint2 r0 = *reinterpret_cast<const uint2*>(g_h + i0 * HID + c);
        uint2 r1 = *reinterpret_cast<const uint2*>(g_h + i1 * HID + c);
        float2 a01 = __half22float2(*reinterpret_cast<__half2*>(&r0.x));
        float2 a23 = __half22float2(*reinterpret_cast<__half2*>(&r0.y));
        float2 b01 = __half22float2(*reinterpret_cast<__half2*>(&r1.x));
        float2 b23 = __half22float2(*reinterpret_cast<__half2*>(&r1.y));
        ax += a01.x + b01.x;
        ay += a01.y + b01.y;
        az += a23.x + b23.x;
        aw += a23.y + b23.y;
    }
    if (j < deg) {
        int i0 = __ldg(bucket + j);
        uint2 r0 = *reinterpret_cast<const uint2*>(g_h + i0 * HID + c);
        float2 a01 = __half22float2(*reinterpret_cast<__half2*>(&r0.x));
        float2 a23 = __half22float2(*reinterpret_cast<__half2*>(&r0.y));
        ax += a01.x; ay += a01.y; az += a23.x; aw += a23.y;
    }

    float nrm = rsqrtf(fmaxf((float)deg, 1.f));
    float4 bb = *reinterpret_cast<const float4*>(b + c);
    float4 v;
    v.x = fmaxf(ax * nrm + bb.x, 0.f);
    v.y = fmaxf(ay * nrm + bb.y, 0.f);
    v.z = fmaxf(az * nrm + bb.z, 0.f);
    v.w = fmaxf(aw * nrm + bb.w, 0.f);
    *reinterpret_cast<float4*>(out + node * HID + c) = v;
}

// ---------------------------------------------------------------------------
extern "C" void kernel_launch(void* const* d_in, const int* in_sizes, int n_in,
                              void* d_out, int out_size) {
    const float* features = (const float*)d_in[0];   // [N, 64]
    const int*   src      = (const int*)  d_in[1];   // [E]
    const int*   dst      = (const int*)  d_in[2];   // [E]
    const float* W        = (const float*)d_in[3];   // [64, 32]
    const float* b        = (const float*)d_in[4];   // [32]
    float*       out      = (float*)d_out;           // [N, 32]

    int n = in_sizes[0] / IN_DIM;                    // 100000
    int e = in_sizes[1];                             // 1600000

    // 0) reset counters via memset nodes
    void* p_degout = nullptr; void* p_degin = nullptr; void* p_total = nullptr;
    cudaGetSymbolAddress(&p_degout, g_degout);
    cudaGetSymbolAddress(&p_degin,  g_degin);
    cudaGetSymbolAddress(&p_total,  g_total);
    cudaMemsetAsync(p_degout, 0, (size_t)n * sizeof(float), 0);
    cudaMemsetAsync(p_degin,  0, (size_t)n * sizeof(float), 0);
    cudaMemsetAsync(p_total,  0, sizeof(int), 0);

    // 1) fused gemm_raw + degrees
    int gemm_blocks = (n + GEMM_ROWS - 1) / GEMM_ROWS;
    int deg_blocks  = ((e >> 2) + 255) / 256;
    int total_blocks = 2 * (gemm_blocks > deg_blocks ? gemm_blocks : deg_blocks);
    fused_gemm_deg_kernel<<<total_blocks, 256>>>(
        (const float4*)features, W, (const int4*)src, (const int4*)dst, n, e);

    // 2) bucket allocation + norm_src applied to h
    int an_threads = n * (HID / 8);
    alloc_norm_kernel<<<(an_threads + 255) / 256, 256>>>(n);

    // 3) fill CSR buckets
    fill_kernel<<<((e >> 2) + 255) / 256, 256>>>((const int4*)src,
                                                 (const int4*)dst, e);

    // 4) aggregate + normalize + bias + relu (8 threads/node, no shuffles)
    agg_kernel<<<(n * 8 + 255) / 256, 256>>>(out, b, n);
}